// round 2
// baseline (speedup 1.0000x reference)
#include <cuda_runtime.h>
#include <math.h>

// ---------------------------------------------------------------------------
// Problem: multi-view edge photometric loss.
// Inputs (metadata order):
//  0 start_points  (N,3)  f32
//  1 end_points    (N,3)  f32
//  2 imgs          (5,H,W) f32
//  3 transformations (S,3,4) f32   S = num_src = 4
//  4 intrinsic     (3,3) f32
//  5 coords_x      (P,)  f32
//  6 coords_y      (P,)  f32
//  7 edge_idx      (P,)  i32   (JAX x64 disabled -> int32; unused: contiguous)
//  8 num_per_edge  (N,)  i32
// Output (flattened f32, tuple order):
//  similarity_loss (S,N) | similarity_mask (S,N) | black_area (N) |
//  p2d1 (P,2) | p2d2 (S,P,2)
// ---------------------------------------------------------------------------

#define MAXE 6144
#define NS 4  // num_src (fixed by problem: 5 images)

__device__ float g_params[5 * MAXE * 8];  // per (cam, edge): p0x,p0y,dx,dy,ux,uy
__device__ int   g_begin[MAXE];

// ------------------------- kernel 0: prefix sum ----------------------------
__global__ void scan_kernel(const int* __restrict__ npe, int n)
{
    __shared__ int ssum[1024];
    int tid = threadIdx.x;
    int chunk = (n + 1023) / 1024;
    int lo = tid * chunk;
    int hi = min(lo + chunk, n);
    if (lo > n) lo = n;
    int local = 0;
    for (int i = lo; i < hi; i++) local += npe[i];
    ssum[tid] = local;
    __syncthreads();
    for (int d = 1; d < 1024; d <<= 1) {
        int t = (tid >= d) ? ssum[tid - d] : 0;
        __syncthreads();
        ssum[tid] += t;
        __syncthreads();
    }
    int run = ssum[tid] - local;  // exclusive prefix at chunk start
    for (int i = lo; i < hi; i++) { g_begin[i] = run; run += npe[i]; }
}

// --------------------- kernel A: per-edge camera params --------------------
__device__ __forceinline__ void store_prm(int cam, int e, int nE,
                                          float p0x, float p0y,
                                          float dx, float dy, float upscale)
{
    float cx = dy, cy = -dx;              // cross([dx,dy,0],[0,0,1]).xy
    float nrm = sqrtf(cx * cx + cy * cy);
    float sc = upscale / (nrm + 1e-6f);
    float* p = &g_params[((size_t)cam * nE + e) * 8];
    p[0] = p0x; p[1] = p0y; p[2] = dx; p[3] = dy; p[4] = cx * sc; p[5] = cy * sc;
}

__global__ void edge_params_kernel(const float* __restrict__ sp,
                                   const float* __restrict__ ep,
                                   const float* __restrict__ K,
                                   const float* __restrict__ trans,
                                   int n_edges, int num_src, float upscale)
{
    int e = blockIdx.x * blockDim.x + threadIdx.x;
    if (e >= n_edges) return;
    float sx = sp[3 * e], sy = sp[3 * e + 1], sz = sp[3 * e + 2];
    float tx = ep[3 * e], ty = ep[3 * e + 1], tz = ep[3 * e + 2];

    // reference camera (intrinsic only)
    {
        float pzs = K[6] * sx + K[7] * sy + K[8] * sz;
        float us  = (K[0] * sx + K[1] * sy + K[2] * sz) / (pzs + 1e-6f);
        float vs  = (K[3] * sx + K[4] * sy + K[5] * sz) / (pzs + 1e-6f);
        float pzt = K[6] * tx + K[7] * ty + K[8] * tz;
        float ut  = (K[0] * tx + K[1] * ty + K[2] * tz) / (pzt + 1e-6f);
        float vt  = (K[3] * tx + K[4] * ty + K[5] * tz) / (pzt + 1e-6f);
        store_prm(0, e, n_edges, us, vs, ut - us, vt - vs, upscale);
    }
    for (int s = 0; s < num_src; s++) {
        const float* T = trans + 12 * s;
        float pzs = T[8] * sx + T[9] * sy + T[10] * sz + T[11];
        float us  = (T[0] * sx + T[1] * sy + T[2] * sz + T[3]) / (pzs + 1e-6f);
        float vs  = (T[4] * sx + T[5] * sy + T[6] * sz + T[7]) / (pzs + 1e-6f);
        float pzt = T[8] * tx + T[9] * ty + T[10] * tz + T[11];
        float ut  = (T[0] * tx + T[1] * ty + T[2] * tz + T[3]) / (pzt + 1e-6f);
        float vt  = (T[4] * tx + T[5] * ty + T[6] * tz + T[7]) / (pzt + 1e-6f);
        store_prm(1 + s, e, n_edges, us, vs, ut - us, vt - vs, upscale);
    }
}

// --------------------------- bilinear sample -------------------------------
__device__ __forceinline__ float bilerp(const float* __restrict__ img,
                                        float u, float v, int W, int H)
{
    float x = u * (float)W - 0.5f;
    float y = v * (float)H - 0.5f;
    float x0f = floorf(x), y0f = floorf(y);
    float wx = x - x0f, wy = y - y0f;
    int x0i = min(max((int)x0f, 0), W - 1);
    int x1i = min(x0i + 1, W - 1);
    int y0i = min(max((int)y0f, 0), H - 1);
    int y1i = min(y0i + 1, H - 1);
    const float* r0 = img + (size_t)y0i * W;
    const float* r1 = img + (size_t)y1i * W;
    float v00 = r0[x0i], v01 = r0[x1i], v10 = r1[x0i], v11 = r1[x1i];
    float top = v00 * (1.0f - wx) + v01 * wx;
    float bot = v10 * (1.0f - wx) + v11 * wx;
    return top * (1.0f - wy) + bot * wy;
}

// --------------------- kernel B: per-point, block-per-edge -----------------
__global__ void __launch_bounds__(256)
point_kernel(const float* __restrict__ cxs, const float* __restrict__ cys,
             const float* __restrict__ imgs,
             const int* __restrict__ npe,
             float* __restrict__ out_loss, float* __restrict__ out_mask,
             float* __restrict__ out_black,
             float* __restrict__ out_p2d1, float* __restrict__ out_p2d2,
             int W, int H, int n_edges, int P)
{
    int e = blockIdx.x;
    __shared__ float prm[5][6];
    __shared__ float redf[8][5];
    __shared__ unsigned redm[8];

    int tid = threadIdx.x;
    if (tid < 30) {
        int cam = tid / 6, j = tid % 6;
        prm[cam][j] = g_params[((size_t)cam * n_edges + e) * 8 + j];
    }
    __syncthreads();

    int b = g_begin[e];
    int n = npe[e];
    const size_t imgHW = (size_t)W * H;

    float ls[NS] = {0.f, 0.f, 0.f, 0.f};
    float bc = 0.f;
    unsigned m = (1u << NS) - 1u;

    for (int i = tid; i < n; i += blockDim.x) {
        int p = b + i;
        float cx = cxs[p], cy = cys[p];

        float u1 = fmaf(prm[0][2], cx, fmaf(prm[0][4], cy, prm[0][0]));
        float v1 = fmaf(prm[0][3], cx, fmaf(prm[0][5], cy, prm[0][1]));
        bool vm1 = (u1 > 0.f) & (u1 < 1.f) & (v1 > 0.f) & (v1 < 1.f);
        float u1c = fminf(fmaxf(u1, 0.f), 0.999999f);
        float v1c = fminf(fmaxf(v1, 0.f), 0.999999f);
        reinterpret_cast<float2*>(out_p2d1)[p] = make_float2(u1c, v1c);
        float s1 = bilerp(imgs, u1c, v1c, W, H);
        if (s1 < 0.01f) bc += 1.f;

#pragma unroll
        for (int s = 0; s < NS; s++) {
            float u = fmaf(prm[s + 1][2], cx, fmaf(prm[s + 1][4], cy, prm[s + 1][0]));
            float v = fmaf(prm[s + 1][3], cx, fmaf(prm[s + 1][5], cy, prm[s + 1][1]));
            bool vm2 = (u > 0.f) & (u < 1.f) & (v > 0.f) & (v < 1.f);
            float uc = fminf(fmaxf(u, 0.f), 0.999999f);
            float vc = fminf(fmaxf(v, 0.f), 0.999999f);
            reinterpret_cast<float2*>(out_p2d2)[(size_t)s * P + p] = make_float2(uc, vc);
            float s2 = bilerp(imgs + (size_t)(s + 1) * imgHW, uc, vc, W, H);
            float d = s2 - s1;
            ls[s] += d * d;
            if (!(vm1 && vm2)) m &= ~(1u << s);
        }
    }

    // warp reduce
#pragma unroll
    for (int off = 16; off > 0; off >>= 1) {
#pragma unroll
        for (int s = 0; s < NS; s++) ls[s] += __shfl_down_sync(0xFFFFFFFFu, ls[s], off);
        bc += __shfl_down_sync(0xFFFFFFFFu, bc, off);
        m &= __shfl_down_sync(0xFFFFFFFFu, m, off);
    }
    int lane = tid & 31, warp = tid >> 5;
    if (lane == 0) {
#pragma unroll
        for (int s = 0; s < NS; s++) redf[warp][s] = ls[s];
        redf[warp][4] = bc;
        redm[warp] = m;
    }
    __syncthreads();
    if (tid == 0) {
        float tls[NS] = {0.f, 0.f, 0.f, 0.f};
        float tbc = 0.f;
        unsigned tm = (1u << NS) - 1u;
        int nw = (blockDim.x + 31) / 32;
        for (int w = 0; w < nw; w++) {
#pragma unroll
            for (int s = 0; s < NS; s++) tls[s] += redf[w][s];
            tbc += redf[w][4];
            tm &= redm[w];
        }
        float cnt = (float)n;
#pragma unroll
        for (int s = 0; s < NS; s++) {
            out_loss[(size_t)s * n_edges + e] = tls[s] / cnt;
            out_mask[(size_t)s * n_edges + e] = ((tm >> s) & 1u) ? 1.f : 0.f;
        }
        out_black[e] = ((tbc / cnt) > 0.5f) ? 1.f : 0.f;
    }
}

// ---------------------------------------------------------------------------
extern "C" void kernel_launch(void* const* d_in, const int* in_sizes, int n_in,
                              void* d_out, int out_size)
{
    const float* start = (const float*)d_in[0];
    const float* end_p = (const float*)d_in[1];
    const float* imgs  = (const float*)d_in[2];
    const float* trans = (const float*)d_in[3];
    const float* K     = (const float*)d_in[4];
    const float* cxs   = (const float*)d_in[5];
    const float* cys   = (const float*)d_in[6];
    const int*   npe   = (const int*)d_in[8];
    float* out = (float*)d_out;

    int n_edges = in_sizes[0] / 3;
    int P       = in_sizes[5];
    int num_src = in_sizes[3] / 12;            // 4
    long long hw = (long long)in_sizes[2] / (num_src + 1);
    int W = (int)(sqrt((double)hw) + 0.5);
    int H = (int)(hw / W);

    // output layout (all f32, tuple order)
    float* out_loss  = out;
    float* out_mask  = out_loss + (size_t)num_src * n_edges;
    float* out_black = out_mask + (size_t)num_src * n_edges;
    float* out_p2d1  = out_black + n_edges;
    float* out_p2d2  = out_p2d1 + 2 * (size_t)P;

    scan_kernel<<<1, 1024>>>(npe, n_edges);
    edge_params_kernel<<<(n_edges + 255) / 256, 256>>>(
        start, end_p, K, trans, n_edges, num_src, 10.0f / (float)W);
    point_kernel<<<n_edges, 256>>>(
        cxs, cys, imgs, npe,
        out_loss, out_mask, out_black, out_p2d1, out_p2d2,
        W, H, n_edges, P);
}